// round 14
// baseline (speedup 1.0000x reference)
#include <cuda_runtime.h>
#include <cuda_bf16.h>
#include <cstdint>
#include <cstddef>

#define N_NODES 50000
#define E_EDGES 800000
#define IN_DIM  128
#define H_DIM   96
#define PN_SCALE 20.0f
#define BN_EPS   1e-5f

// ---------------- scratch (static device globals; no allocation) ----------------
__device__ float g_z[(size_t)N_NODES * H_DIM];      // z = h0 + agg
__device__ float g_h[(size_t)N_NODES * H_DIM];      // h = z@W1^T + b1 (pre-BN)
__device__ float g_stats[3 * H_DIM];                // bn sum | bn sumsq | l1 col sum
__device__ int   g_cnt[N_NODES];                    // degree counts (zeroed each pass)
__device__ int   g_start[N_NODES + 1];              // CSR row offsets
__device__ int   g_cursor[N_NODES];                 // fill cursors
__device__ int   g_csr[E_EDGES];                    // src ids grouped by dst
__device__ int   g_bsum[256];                       // scan block sums

// ---------------- helpers ----------------
__device__ __forceinline__ float to_tf32(float x) {
    uint32_t u;
    asm("cvt.rna.tf32.f32 %0, %1;" : "=r"(u) : "f"(x));
    return __uint_as_float(u);
}

__device__ __forceinline__ void mma_tf32(float c[4], const uint32_t a[4], const uint32_t b[2]) {
    asm volatile(
        "mma.sync.aligned.m16n8k8.row.col.f32.tf32.tf32.f32 "
        "{%0,%1,%2,%3},{%4,%5,%6,%7},{%8,%9},{%0,%1,%2,%3};"
        : "+f"(c[0]), "+f"(c[1]), "+f"(c[2]), "+f"(c[3])
        : "r"(a[0]), "r"(a[1]), "r"(a[2]), "r"(a[3]), "r"(b[0]), "r"(b[1]));
}

__device__ __forceinline__ int warp_iscan(int v, int lane) {
    #pragma unroll
    for (int o = 1; o < 32; o <<= 1) {
        int t = __shfl_up_sync(0xffffffffu, v, o);
        if (lane >= o) v += t;
    }
    return v;
}

// ---------------- CSR build kernels ----------------
// hist: 8 edges per thread via two int4 loads of the dst half
__global__ __launch_bounds__(256) void hist_kernel(const int* __restrict__ ei) {
    int i = blockIdx.x * 256 + threadIdx.x;
    int base = i * 8;
    if (base < E_EDGES) {
        int4 da = *(const int4*)(ei + E_EDGES + base);
        int4 db = *(const int4*)(ei + E_EDGES + base + 4);
        atomicAdd(&g_cnt[da.x], 1);
        atomicAdd(&g_cnt[da.y], 1);
        atomicAdd(&g_cnt[da.z], 1);
        atomicAdd(&g_cnt[da.w], 1);
        atomicAdd(&g_cnt[db.x], 1);
        atomicAdd(&g_cnt[db.y], 1);
        atomicAdd(&g_cnt[db.z], 1);
        atomicAdd(&g_cnt[db.w], 1);
    }
}

// exclusive scan of g_cnt in 256-chunks (in place); g_bsum[b] = block total
__global__ void scan_local_kernel() {
    __shared__ int wsum[8];
    int tid = threadIdx.x, lane = tid & 31, w = tid >> 5;
    int i = blockIdx.x * 256 + tid;
    int v = (i < N_NODES) ? g_cnt[i] : 0;
    int inc = warp_iscan(v, lane);
    if (lane == 31) wsum[w] = inc;
    __syncthreads();
    if (w == 0) {
        int t = (lane < 8) ? wsum[lane] : 0;
        t = warp_iscan(t, lane);
        if (lane < 8) wsum[lane] = t;
    }
    __syncthreads();
    int off = w ? wsum[w - 1] : 0;
    if (i < N_NODES) g_cnt[i] = off + inc - v;
    if (tid == 255) g_bsum[blockIdx.x] = wsum[7];
}

// scan_add: block b sums g_bsum[j<b] itself, writes start/cursor, re-zeroes g_cnt
__global__ void scan_add_kernel(int nblocks) {
    __shared__ int ws[8];
    int tid = threadIdx.x, lane = tid & 31, w = tid >> 5;
    int b = blockIdx.x;
    int part = 0;
    for (int j = tid; j < b; j += 256) part += g_bsum[j];
    #pragma unroll
    for (int o = 16; o; o >>= 1) part += __shfl_xor_sync(0xffffffffu, part, o);
    if (lane == 0) ws[w] = part;
    __syncthreads();
    int boff = ws[0] + ws[1] + ws[2] + ws[3] + ws[4] + ws[5] + ws[6] + ws[7];

    int i = b * 256 + tid;
    if (i < N_NODES) {
        int st = g_cnt[i] + boff;
        g_start[i] = st;
        g_cursor[i] = st;
        g_cnt[i] = 0;
    }
    if (i == 0) g_start[N_NODES] = E_EDGES;
}

// fill: 8 edges per thread; all 8 cursor atomics issued before the 8 stores (ILP)
__global__ __launch_bounds__(256) void fill_kernel(const int* __restrict__ ei) {
    int i = blockIdx.x * 256 + threadIdx.x;
    int base = i * 8;
    if (base >= E_EDGES) return;
    int4 sa = *(const int4*)(ei + base);
    int4 sb = *(const int4*)(ei + base + 4);
    int4 da = *(const int4*)(ei + E_EDGES + base);
    int4 db = *(const int4*)(ei + E_EDGES + base + 4);
    int p0 = atomicAdd(&g_cursor[da.x], 1);
    int p1 = atomicAdd(&g_cursor[da.y], 1);
    int p2 = atomicAdd(&g_cursor[da.z], 1);
    int p3 = atomicAdd(&g_cursor[da.w], 1);
    int p4 = atomicAdd(&g_cursor[db.x], 1);
    int p5 = atomicAdd(&g_cursor[db.y], 1);
    int p6 = atomicAdd(&g_cursor[db.z], 1);
    int p7 = atomicAdd(&g_cursor[db.w], 1);
    g_csr[p0] = sa.x;
    g_csr[p1] = sa.y;
    g_csr[p2] = sa.z;
    g_csr[p3] = sa.w;
    g_csr[p4] = sb.x;
    g_csr[p5] = sb.y;
    g_csr[p6] = sb.z;
    g_csr[p7] = sb.w;
}

// ---------------- gather-aggregate: g_z[n] = h0[n] + sum_{s in nbrs(n)} h0[s] --------
// one warp per node; lanes 0..23 each own a float4; neighbor loop unrolled x4
__global__ __launch_bounds__(256) void aggregate_kernel(const float* __restrict__ h0) {
    int node = blockIdx.x * 8 + (threadIdx.x >> 5);
    if (node >= N_NODES) return;
    int lane = threadIdx.x & 31;
    int beg = g_start[node], end = g_start[node + 1];
    float4 acc = make_float4(0.f, 0.f, 0.f, 0.f);
    const int c4 = (lane < 24) ? (lane << 2) : 0;
    for (int base = beg; base < end; base += 32) {
        int m = min(32, end - base);
        int si = (base + lane < end) ? g_csr[base + lane] : 0;
        int it = 0;
        for (; it + 4 <= m; it += 4) {
            int s0 = __shfl_sync(0xffffffffu, si, it);
            int s1 = __shfl_sync(0xffffffffu, si, it + 1);
            int s2 = __shfl_sync(0xffffffffu, si, it + 2);
            int s3 = __shfl_sync(0xffffffffu, si, it + 3);
            if (lane < 24) {
                float4 v0 = *(const float4*)(h0 + (size_t)s0 * H_DIM + c4);
                float4 v1 = *(const float4*)(h0 + (size_t)s1 * H_DIM + c4);
                float4 v2 = *(const float4*)(h0 + (size_t)s2 * H_DIM + c4);
                float4 v3 = *(const float4*)(h0 + (size_t)s3 * H_DIM + c4);
                acc.x += (v0.x + v1.x) + (v2.x + v3.x);
                acc.y += (v0.y + v1.y) + (v2.y + v3.y);
                acc.z += (v0.z + v1.z) + (v2.z + v3.z);
                acc.w += (v0.w + v1.w) + (v2.w + v3.w);
            }
        }
        for (; it < m; it++) {
            int s = __shfl_sync(0xffffffffu, si, it);
            if (lane < 24) {
                float4 v = *(const float4*)(h0 + (size_t)s * H_DIM + c4);
                acc.x += v.x; acc.y += v.y; acc.z += v.z; acc.w += v.w;
            }
        }
    }
    if (lane < 24) {
        float4 h = *(const float4*)(h0 + (size_t)node * H_DIM + c4);
        *(float4*)(g_z + (size_t)node * H_DIM + c4) =
            make_float4(h.x + acc.x, h.y + acc.y, h.z + acc.z, h.w + acc.w);
    }
}

// ---------------- single-shot full-K tf32 GEMM ----------------------------------------
// out[M,96] = A[M,KD] @ W[96,KD]^T + bias.  Whole BM-row A strip + whole W in smem,
// one batched load phase, one sync, MMA burst. STRIDE = KD+4 -> conflict-free LDS.
template<int KD, int BM, int NT, int MINB, int AMODE, int DMODE, bool TRANS, int STATS>
__global__ __launch_bounds__(NT, MINB) void gemm_kernel(
    const float* __restrict__ A, const float* __restrict__ W,
    const float* __restrict__ bias, const float* __restrict__ gamma,
    const float* __restrict__ beta, float* __restrict__ outp, int M)
{
    constexpr int STRIDE = KD + 4;
    constexpr int F4 = KD / 4;
    constexpr int WARPS_M = NT / 64;
    static_assert(BM == WARPS_M * 32, "BM must match warp layout");

    extern __shared__ float smem[];
    float* As      = smem;
    float* Bs      = As + BM * STRIDE;
    float* s_scale = Bs + 96 * STRIDE;
    float* s_shift = s_scale + 96;
    float* sred    = s_shift + 96;
    float* sred2   = sred + WARPS_M * 96;

    const float* Aptr = (AMODE == 0) ? A : ((AMODE == 1) ? g_z : g_h);

    const int tid = threadIdx.x;
    const int lane = tid & 31;
    const int wid = tid >> 5;
    const int warp_n = wid & 1;
    const int warp_m = wid >> 1;
    const int g = lane >> 2;
    const int q = lane & 3;
    const int row0 = blockIdx.x * BM;

    if (AMODE == 0 && blockIdx.x == 0) {
        for (int i = tid; i < 3 * H_DIM; i += NT) g_stats[i] = 0.0f;
    }

    if (TRANS) {
        if (tid < H_DIM) {
            const float invN = 1.0f / (float)N_NODES;
            float mean = g_stats[tid] * invN;
            float var  = g_stats[H_DIM + tid] * invN - mean * mean;
            float sc = gamma[tid] * rsqrtf(var + BN_EPS);
            s_scale[tid] = sc;
            s_shift[tid] = beta[tid] - mean * sc;
        }
        __syncthreads();
    }

    // ---- batched load phase ----
    #pragma unroll
    for (int i = 0; i < BM * F4 / NT; i++) {
        int id = tid + i * NT;
        int row = id / F4;
        int kq = (id - row * F4) * 4;
        int grow = row0 + row;
        float4 v = make_float4(0.f, 0.f, 0.f, 0.f);
        if (grow < M) v = *(const float4*)(Aptr + (size_t)grow * KD + kq);
        if (TRANS) {
            v.x = fmaxf(0.f, fmaf(v.x, s_scale[kq + 0], s_shift[kq + 0]));
            v.y = fmaxf(0.f, fmaf(v.y, s_scale[kq + 1], s_shift[kq + 1]));
            v.z = fmaxf(0.f, fmaf(v.z, s_scale[kq + 2], s_shift[kq + 2]));
            v.w = fmaxf(0.f, fmaf(v.w, s_scale[kq + 3], s_shift[kq + 3]));
        }
        *(float4*)&As[row * STRIDE + kq] =
            make_float4(to_tf32(v.x), to_tf32(v.y), to_tf32(v.z), to_tf32(v.w));
    }
    #pragma unroll
    for (int i = 0; i < (96 * F4 + NT - 1) / NT; i++) {
        int id = tid + i * NT;
        if (id < 96 * F4) {
            int n = id / F4;
            int kq = (id - n * F4) * 4;
            float4 v = *(const float4*)(W + (size_t)n * KD + kq);
            *(float4*)&Bs[n * STRIDE + kq] =
                make_float4(to_tf32(v.x), to_tf32(v.y), to_tf32(v.z), to_tf32(v.w));
        }
    }
    __syncthreads();

    // ---- MMA burst ----
    float acc[2][6][4];
    #pragma unroll
    for (int mt = 0; mt < 2; mt++)
        #pragma unroll
        for (int nt = 0; nt < 6; nt++)
            #pragma unroll
            for (int j = 0; j < 4; j++) acc[mt][nt][j] = 0.0f;

    const int m_base0 = warp_m * 32 + g;
    const int n_base  = warp_n * 48 + g;

    #pragma unroll
    for (int kb = 0; kb < KD; kb += 8) {
        uint32_t afrag[2][4];
        uint32_t bfrag[6][2];
        #pragma unroll
        for (int mt = 0; mt < 2; mt++) {
            const float* ap = &As[(m_base0 + mt * 16) * STRIDE + kb + q];
            afrag[mt][0] = __float_as_uint(ap[0]);
            afrag[mt][1] = __float_as_uint(ap[8 * STRIDE]);
            afrag[mt][2] = __float_as_uint(ap[4]);
            afrag[mt][3] = __float_as_uint(ap[8 * STRIDE + 4]);
        }
        #pragma unroll
        for (int nt = 0; nt < 6; nt++) {
            const float* bp = &Bs[(n_base + nt * 8) * STRIDE + kb + q];
            bfrag[nt][0] = __float_as_uint(bp[0]);
            bfrag[nt][1] = __float_as_uint(bp[4]);
        }
        #pragma unroll
        for (int mt = 0; mt < 2; mt++)
            #pragma unroll
            for (int nt = 0; nt < 6; nt++)
                mma_tf32(acc[mt][nt], afrag[mt], bfrag[nt]);
    }

    // ---- epilogue ----
    float2 bb[6];
    #pragma unroll
    for (int nt = 0; nt < 6; nt++)
        bb[nt] = *(const float2*)(bias + warp_n * 48 + nt * 8 + 2 * q);

    float csum[6][2];
    float csq [6][2];
    #pragma unroll
    for (int nt = 0; nt < 6; nt++)
        #pragma unroll
        for (int j = 0; j < 2; j++) { csum[nt][j] = 0.f; csq[nt][j] = 0.f; }

    #pragma unroll
    for (int nt = 0; nt < 6; nt++) {
        const int col0 = warp_n * 48 + nt * 8 + 2 * q;
        #pragma unroll
        for (int mt = 0; mt < 2; mt++) {
            const int grow0 = row0 + warp_m * 32 + mt * 16 + g;
            const int grow1 = grow0 + 8;
            float v0 = acc[mt][nt][0] + bb[nt].x;
            float v1 = acc[mt][nt][1] + bb[nt].y;
            float v2 = acc[mt][nt][2] + bb[nt].x;
            float v3 = acc[mt][nt][3] + bb[nt].y;
            if (grow0 < M) {
                float2 p = make_float2(v0, v1);
                size_t ofs = (size_t)grow0 * H_DIM + col0;
                if (DMODE == 2) *(float2*)(g_h + ofs) = p;
                else            *(float2*)(outp + ofs) = p;
                if (STATS) {
                    csum[nt][0] += v0; csum[nt][1] += v1;
                    if (STATS == 1) { csq[nt][0] += v0 * v0; csq[nt][1] += v1 * v1; }
                }
            }
            if (grow1 < M) {
                float2 p = make_float2(v2, v3);
                size_t ofs = (size_t)grow1 * H_DIM + col0;
                if (DMODE == 2) *(float2*)(g_h + ofs) = p;
                else            *(float2*)(outp + ofs) = p;
                if (STATS) {
                    csum[nt][0] += v2; csum[nt][1] += v3;
                    if (STATS == 1) { csq[nt][0] += v2 * v2; csq[nt][1] += v3 * v3; }
                }
            }
        }
    }

    if (STATS) {
        #pragma unroll
        for (int nt = 0; nt < 6; nt++) {
            #pragma unroll
            for (int j = 0; j < 2; j++) {
                float s = csum[nt][j];
                s += __shfl_xor_sync(0xffffffffu, s, 4);
                s += __shfl_xor_sync(0xffffffffu, s, 8);
                s += __shfl_xor_sync(0xffffffffu, s, 16);
                float qq = 0.f;
                if (STATS == 1) {
                    qq = csq[nt][j];
                    qq += __shfl_xor_sync(0xffffffffu, qq, 4);
                    qq += __shfl_xor_sync(0xffffffffu, qq, 8);
                    qq += __shfl_xor_sync(0xffffffffu, qq, 16);
                }
                if (lane < 4) {
                    int col = warp_n * 48 + nt * 8 + 2 * q + j;
                    sred[warp_m * 96 + col] = s;
                    if (STATS == 1) sred2[warp_m * 96 + col] = qq;
                }
            }
        }
        __syncthreads();
        if (tid < H_DIM) {
            float s = 0.f, qq = 0.f;
            #pragma unroll
            for (int t = 0; t < WARPS_M; t++) {
                s += sred[t * 96 + tid];
                if (STATS == 1) qq += sred2[t * 96 + tid];
            }
            if (STATS == 1) {
                atomicAdd(&g_stats[tid], s);
                atomicAdd(&g_stats[H_DIM + tid], qq);
            } else {
                atomicAdd(&g_stats[2 * H_DIM + tid], s);
            }
        }
    }
}

// ---------------- PairNorm (in place on d_out l1 region) ----------------
__global__ __launch_bounds__(256) void pairnorm_kernel(float* __restrict__ out) {
    int row = blockIdx.x * 8 + (threadIdx.x >> 5);
    if (row >= N_NODES) return;
    int lane = threadIdx.x & 31;
    float* r = out + (size_t)row * H_DIM;
    float v0 = r[lane], v1 = r[lane + 32], v2 = r[lane + 64];
    float ss = v0 * v0 + v1 * v1 + v2 * v2;
    #pragma unroll
    for (int o = 16; o; o >>= 1) ss += __shfl_xor_sync(0xffffffffu, ss, o);
    float sc = PN_SCALE * rsqrtf(1e-6f + ss);
    const float invN = 1.0f / (float)N_NODES;
    r[lane]      = v0 * sc - g_stats[2 * H_DIM + lane]      * invN;
    r[lane + 32] = v1 * sc - g_stats[2 * H_DIM + lane + 32] * invN;
    r[lane + 64] = v2 * sc - g_stats[2 * H_DIM + lane + 64] * invN;
}

// ---------------- launch ----------------
static inline int gemm_smem_bytes(int KD, int BM, int NT) {
    int stride = KD + 4;
    int wm = NT / 64;
    return (BM * stride + 96 * stride + 192 + 2 * wm * 96) * 4;
}

extern "C" void kernel_launch(void* const* d_in, const int* in_sizes, int n_in,
                              void* d_out, int out_size) {
    const float* x     = (const float*)d_in[0];
    const int*   ei    = (const int*)  d_in[1];
    const float* W0    = (const float*)d_in[2];
    const float* b0    = (const float*)d_in[3];
    const float* W1    = (const float*)d_in[4];
    const float* b1    = (const float*)d_in[5];
    const float* gamma = (const float*)d_in[6];
    const float* beta  = (const float*)d_in[7];
    const float* W2    = (const float*)d_in[8];
    const float* b2    = (const float*)d_in[9];

    float* l1 = (float*)d_out;                           // [N, H]
    float* h0 = (float*)d_out + (size_t)N_NODES * H_DIM; // [N, H]

    const int smem0 = gemm_smem_bytes(IN_DIM, 96, 192);  // 104448
    const int smemH = gemm_smem_bytes(H_DIM, 128, 256);  // 93440

    cudaFuncSetAttribute(gemm_kernel<IN_DIM, 96, 192, 2, 0, 0, false, 0>,
                         cudaFuncAttributeMaxDynamicSharedMemorySize, smem0);
    cudaFuncSetAttribute(gemm_kernel<H_DIM, 128, 256, 2, 1, 2, false, 1>,
                         cudaFuncAttributeMaxDynamicSharedMemorySize, smemH);
    cudaFuncSetAttribute(gemm_kernel<H_DIM, 128, 256, 2, 2, 0, true, 2>,
                         cudaFuncAttributeMaxDynamicSharedMemorySize, smemH);

    // host-side resources for fork-join (created once; device work is identical
    // on every call — no device state, no allocation, no call-dependent work)
    static cudaStream_t s_side = nullptr;
    static cudaEvent_t  ev_fork = nullptr, ev_join = nullptr;
    if (s_side == nullptr) {
        cudaStreamCreateWithFlags(&s_side, cudaStreamNonBlocking);
        cudaEventCreateWithFlags(&ev_fork, cudaEventDisableTiming);
        cudaEventCreateWithFlags(&ev_join, cudaEventDisableTiming);
    }

    const int nb_nodes = (N_NODES + 255) / 256;          // 196
    const int nb_oct   = (E_EDGES / 8 + 255) / 256;      // 391

    // ---- fork: CSR build on side stream, concurrent with gemm0 ----
    cudaEventRecord(ev_fork, 0);
    cudaStreamWaitEvent(s_side, ev_fork, 0);

    hist_kernel<<<nb_oct, 256, 0, s_side>>>(ei);
    scan_local_kernel<<<nb_nodes, 256, 0, s_side>>>();
    scan_add_kernel<<<nb_nodes, 256, 0, s_side>>>(nb_nodes);
    fill_kernel<<<nb_oct, 256, 0, s_side>>>(ei);
    cudaEventRecord(ev_join, s_side);

    // ---- main stream: h0 = x @ W0^T + b0 (also zeroes g_stats); 2 CTAs/SM ----
    gemm_kernel<IN_DIM, 96, 192, 2, 0, 0, false, 0><<<(N_NODES + 95) / 96, 192, smem0>>>(
        x, W0, b0, nullptr, nullptr, h0, N_NODES);

    // ---- join: aggregate needs both h0 and the CSR ----
    cudaStreamWaitEvent(0, ev_join, 0);

    // ---- g_z = h0 + gather-sum over CSR ----
    aggregate_kernel<<<(N_NODES + 7) / 8, 256>>>(h0);

    // ---- g_h = g_z @ W1^T + b1 ; fused BN stats ----
    gemm_kernel<H_DIM, 128, 256, 2, 1, 2, false, 1><<<(N_NODES + 127) / 128, 256, smemH>>>(
        nullptr, W1, b1, nullptr, nullptr, nullptr, N_NODES);

    // ---- l1 = relu(bn(g_h)) @ W2^T + b2 ; BN finalize in prologue; col-sum fused ----
    gemm_kernel<H_DIM, 128, 256, 2, 2, 0, true, 2><<<(N_NODES + 127) / 128, 256, smemH>>>(
        nullptr, W2, b2, gamma, beta, l1, N_NODES);

    // ---- PairNorm in place ----
    pairnorm_kernel<<<(N_NODES + 7) / 8, 256>>>(l1);
}

// round 16
// speedup vs baseline: 1.4067x; 1.4067x over previous
#include <cuda_runtime.h>
#include <cuda_bf16.h>
#include <cstdint>
#include <cstddef>

#define N_NODES 50000
#define E_EDGES 800000
#define IN_DIM  128
#define H_DIM   96
#define PN_SCALE 20.0f
#define BN_EPS   1e-5f

// ---------------- scratch (static device globals; no allocation) ----------------
__device__ float g_z[(size_t)N_NODES * H_DIM];      // z = h0 + agg
__device__ float g_h[(size_t)N_NODES * H_DIM];      // h = z@W1^T + b1 (pre-BN)
__device__ float g_stats[3 * H_DIM];                // bn sum | bn sumsq | l1 col sum
__device__ int   g_cnt[N_NODES];                    // degree counts (zeroed each pass)
__device__ int   g_start[N_NODES + 1];              // CSR row offsets
__device__ int   g_cursor[N_NODES];                 // fill cursors
__device__ int   g_csr[E_EDGES];                    // src ids grouped by dst
__device__ int   g_bsum[256];                       // scan block sums

// ---------------- helpers ----------------
__device__ __forceinline__ float to_tf32(float x) {
    uint32_t u;
    asm("cvt.rna.tf32.f32 %0, %1;" : "=r"(u) : "f"(x));
    return __uint_as_float(u);
}

__device__ __forceinline__ void mma_tf32(float c[4], const uint32_t a[4], const uint32_t b[2]) {
    asm volatile(
        "mma.sync.aligned.m16n8k8.row.col.f32.tf32.tf32.f32 "
        "{%0,%1,%2,%3},{%4,%5,%6,%7},{%8,%9},{%0,%1,%2,%3};"
        : "+f"(c[0]), "+f"(c[1]), "+f"(c[2]), "+f"(c[3])
        : "r"(a[0]), "r"(a[1]), "r"(a[2]), "r"(a[3]), "r"(b[0]), "r"(b[1]));
}

__device__ __forceinline__ int warp_iscan(int v, int lane) {
    #pragma unroll
    for (int o = 1; o < 32; o <<= 1) {
        int t = __shfl_up_sync(0xffffffffu, v, o);
        if (lane >= o) v += t;
    }
    return v;
}

// ---------------- CSR build kernels ----------------
// hist: 4 edges per thread via int4 load of dst half (RED, no return -> throughput-bound)
__global__ __launch_bounds__(256) void hist_kernel(const int* __restrict__ ei) {
    int i = blockIdx.x * 256 + threadIdx.x;
    if (i * 4 < E_EDGES) {
        int4 d = *(const int4*)(ei + E_EDGES + i * 4);
        atomicAdd(&g_cnt[d.x], 1);
        atomicAdd(&g_cnt[d.y], 1);
        atomicAdd(&g_cnt[d.z], 1);
        atomicAdd(&g_cnt[d.w], 1);
    }
}

// exclusive scan of g_cnt in 256-chunks (in place); g_bsum[b] = block total
__global__ void scan_local_kernel() {
    __shared__ int wsum[8];
    int tid = threadIdx.x, lane = tid & 31, w = tid >> 5;
    int i = blockIdx.x * 256 + tid;
    int v = (i < N_NODES) ? g_cnt[i] : 0;
    int inc = warp_iscan(v, lane);
    if (lane == 31) wsum[w] = inc;
    __syncthreads();
    if (w == 0) {
        int t = (lane < 8) ? wsum[lane] : 0;
        t = warp_iscan(t, lane);
        if (lane < 8) wsum[lane] = t;
    }
    __syncthreads();
    int off = w ? wsum[w - 1] : 0;
    if (i < N_NODES) g_cnt[i] = off + inc - v;
    if (tid == 255) g_bsum[blockIdx.x] = wsum[7];
}

// scan_add: block b sums g_bsum[j<b] itself, writes start/cursor, re-zeroes g_cnt
__global__ void scan_add_kernel(int nblocks) {
    __shared__ int ws[8];
    int tid = threadIdx.x, lane = tid & 31, w = tid >> 5;
    int b = blockIdx.x;
    int part = 0;
    for (int j = tid; j < b; j += 256) part += g_bsum[j];
    #pragma unroll
    for (int o = 16; o; o >>= 1) part += __shfl_xor_sync(0xffffffffu, part, o);
    if (lane == 0) ws[w] = part;
    __syncthreads();
    int boff = ws[0] + ws[1] + ws[2] + ws[3] + ws[4] + ws[5] + ws[6] + ws[7];

    int i = b * 256 + tid;
    if (i < N_NODES) {
        int st = g_cnt[i] + boff;
        g_start[i] = st;
        g_cursor[i] = st;
        g_cnt[i] = 0;
    }
    if (i == 0) g_start[N_NODES] = E_EDGES;
}

// fill: ONE edge per thread — no per-thread atomic chain; latency hidden by
// maximal resident-warp count (800K threads).
__global__ __launch_bounds__(256) void fill_kernel(const int* __restrict__ ei) {
    int e = blockIdx.x * 256 + threadIdx.x;
    if (e < E_EDGES) {
        int s = __ldg(ei + e);
        int d = __ldg(ei + E_EDGES + e);
        g_csr[atomicAdd(&g_cursor[d], 1)] = s;
    }
}

// ---------------- gather-aggregate: g_z[n] = h0[n] + sum_{s in nbrs(n)} h0[s] --------
// one warp per node; lanes 0..23 each own a float4; neighbor loop unrolled x4
__global__ __launch_bounds__(256) void aggregate_kernel(const float* __restrict__ h0) {
    int node = blockIdx.x * 8 + (threadIdx.x >> 5);
    if (node >= N_NODES) return;
    int lane = threadIdx.x & 31;
    int beg = g_start[node], end = g_start[node + 1];
    float4 acc = make_float4(0.f, 0.f, 0.f, 0.f);
    const int c4 = (lane < 24) ? (lane << 2) : 0;
    for (int base = beg; base < end; base += 32) {
        int m = min(32, end - base);
        int si = (base + lane < end) ? g_csr[base + lane] : 0;
        int it = 0;
        for (; it + 4 <= m; it += 4) {
            int s0 = __shfl_sync(0xffffffffu, si, it);
            int s1 = __shfl_sync(0xffffffffu, si, it + 1);
            int s2 = __shfl_sync(0xffffffffu, si, it + 2);
            int s3 = __shfl_sync(0xffffffffu, si, it + 3);
            if (lane < 24) {
                float4 v0 = *(const float4*)(h0 + (size_t)s0 * H_DIM + c4);
                float4 v1 = *(const float4*)(h0 + (size_t)s1 * H_DIM + c4);
                float4 v2 = *(const float4*)(h0 + (size_t)s2 * H_DIM + c4);
                float4 v3 = *(const float4*)(h0 + (size_t)s3 * H_DIM + c4);
                acc.x += (v0.x + v1.x) + (v2.x + v3.x);
                acc.y += (v0.y + v1.y) + (v2.y + v3.y);
                acc.z += (v0.z + v1.z) + (v2.z + v3.z);
                acc.w += (v0.w + v1.w) + (v2.w + v3.w);
            }
        }
        for (; it < m; it++) {
            int s = __shfl_sync(0xffffffffu, si, it);
            if (lane < 24) {
                float4 v = *(const float4*)(h0 + (size_t)s * H_DIM + c4);
                acc.x += v.x; acc.y += v.y; acc.z += v.z; acc.w += v.w;
            }
        }
    }
    if (lane < 24) {
        float4 h = *(const float4*)(h0 + (size_t)node * H_DIM + c4);
        *(float4*)(g_z + (size_t)node * H_DIM + c4) =
            make_float4(h.x + acc.x, h.y + acc.y, h.z + acc.z, h.w + acc.w);
    }
}

// ---------------- single-shot full-K tf32 GEMM ----------------------------------------
// out[M,96] = A[M,KD] @ W[96,KD]^T + bias.  Whole BM-row A strip + whole W in smem,
// one batched load phase, one sync, MMA burst. STRIDE = KD+4 -> conflict-free LDS.
template<int KD, int BM, int NT, int MINB, int AMODE, int DMODE, bool TRANS, int STATS>
__global__ __launch_bounds__(NT, MINB) void gemm_kernel(
    const float* __restrict__ A, const float* __restrict__ W,
    const float* __restrict__ bias, const float* __restrict__ gamma,
    const float* __restrict__ beta, float* __restrict__ outp, int M)
{
    constexpr int STRIDE = KD + 4;
    constexpr int F4 = KD / 4;
    constexpr int WARPS_M = NT / 64;
    static_assert(BM == WARPS_M * 32, "BM must match warp layout");

    extern __shared__ float smem[];
    float* As      = smem;
    float* Bs      = As + BM * STRIDE;
    float* s_scale = Bs + 96 * STRIDE;
    float* s_shift = s_scale + 96;
    float* sred    = s_shift + 96;
    float* sred2   = sred + WARPS_M * 96;

    const float* Aptr = (AMODE == 0) ? A : ((AMODE == 1) ? g_z : g_h);

    const int tid = threadIdx.x;
    const int lane = tid & 31;
    const int wid = tid >> 5;
    const int warp_n = wid & 1;
    const int warp_m = wid >> 1;
    const int g = lane >> 2;
    const int q = lane & 3;
    const int row0 = blockIdx.x * BM;

    if (AMODE == 0 && blockIdx.x == 0) {
        for (int i = tid; i < 3 * H_DIM; i += NT) g_stats[i] = 0.0f;
    }

    if (TRANS) {
        if (tid < H_DIM) {
            const float invN = 1.0f / (float)N_NODES;
            float mean = g_stats[tid] * invN;
            float var  = g_stats[H_DIM + tid] * invN - mean * mean;
            float sc = gamma[tid] * rsqrtf(var + BN_EPS);
            s_scale[tid] = sc;
            s_shift[tid] = beta[tid] - mean * sc;
        }
        __syncthreads();
    }

    // ---- batched load phase ----
    #pragma unroll
    for (int i = 0; i < BM * F4 / NT; i++) {
        int id = tid + i * NT;
        int row = id / F4;
        int kq = (id - row * F4) * 4;
        int grow = row0 + row;
        float4 v = make_float4(0.f, 0.f, 0.f, 0.f);
        if (grow < M) v = *(const float4*)(Aptr + (size_t)grow * KD + kq);
        if (TRANS) {
            v.x = fmaxf(0.f, fmaf(v.x, s_scale[kq + 0], s_shift[kq + 0]));
            v.y = fmaxf(0.f, fmaf(v.y, s_scale[kq + 1], s_shift[kq + 1]));
            v.z = fmaxf(0.f, fmaf(v.z, s_scale[kq + 2], s_shift[kq + 2]));
            v.w = fmaxf(0.f, fmaf(v.w, s_scale[kq + 3], s_shift[kq + 3]));
        }
        *(float4*)&As[row * STRIDE + kq] =
            make_float4(to_tf32(v.x), to_tf32(v.y), to_tf32(v.z), to_tf32(v.w));
    }
    #pragma unroll
    for (int i = 0; i < (96 * F4 + NT - 1) / NT; i++) {
        int id = tid + i * NT;
        if (id < 96 * F4) {
            int n = id / F4;
            int kq = (id - n * F4) * 4;
            float4 v = *(const float4*)(W + (size_t)n * KD + kq);
            *(float4*)&Bs[n * STRIDE + kq] =
                make_float4(to_tf32(v.x), to_tf32(v.y), to_tf32(v.z), to_tf32(v.w));
        }
    }
    __syncthreads();

    // ---- MMA burst ----
    float acc[2][6][4];
    #pragma unroll
    for (int mt = 0; mt < 2; mt++)
        #pragma unroll
        for (int nt = 0; nt < 6; nt++)
            #pragma unroll
            for (int j = 0; j < 4; j++) acc[mt][nt][j] = 0.0f;

    const int m_base0 = warp_m * 32 + g;
    const int n_base  = warp_n * 48 + g;

    #pragma unroll
    for (int kb = 0; kb < KD; kb += 8) {
        uint32_t afrag[2][4];
        uint32_t bfrag[6][2];
        #pragma unroll
        for (int mt = 0; mt < 2; mt++) {
            const float* ap = &As[(m_base0 + mt * 16) * STRIDE + kb + q];
            afrag[mt][0] = __float_as_uint(ap[0]);
            afrag[mt][1] = __float_as_uint(ap[8 * STRIDE]);
            afrag[mt][2] = __float_as_uint(ap[4]);
            afrag[mt][3] = __float_as_uint(ap[8 * STRIDE + 4]);
        }
        #pragma unroll
        for (int nt = 0; nt < 6; nt++) {
            const float* bp = &Bs[(n_base + nt * 8) * STRIDE + kb + q];
            bfrag[nt][0] = __float_as_uint(bp[0]);
            bfrag[nt][1] = __float_as_uint(bp[4]);
        }
        #pragma unroll
        for (int mt = 0; mt < 2; mt++)
            #pragma unroll
            for (int nt = 0; nt < 6; nt++)
                mma_tf32(acc[mt][nt], afrag[mt], bfrag[nt]);
    }

    // ---- epilogue ----
    float2 bb[6];
    #pragma unroll
    for (int nt = 0; nt < 6; nt++)
        bb[nt] = *(const float2*)(bias + warp_n * 48 + nt * 8 + 2 * q);

    float csum[6][2];
    float csq [6][2];
    #pragma unroll
    for (int nt = 0; nt < 6; nt++)
        #pragma unroll
        for (int j = 0; j < 2; j++) { csum[nt][j] = 0.f; csq[nt][j] = 0.f; }

    #pragma unroll
    for (int nt = 0; nt < 6; nt++) {
        const int col0 = warp_n * 48 + nt * 8 + 2 * q;
        #pragma unroll
        for (int mt = 0; mt < 2; mt++) {
            const int grow0 = row0 + warp_m * 32 + mt * 16 + g;
            const int grow1 = grow0 + 8;
            float v0 = acc[mt][nt][0] + bb[nt].x;
            float v1 = acc[mt][nt][1] + bb[nt].y;
            float v2 = acc[mt][nt][2] + bb[nt].x;
            float v3 = acc[mt][nt][3] + bb[nt].y;
            if (grow0 < M) {
                float2 p = make_float2(v0, v1);
                size_t ofs = (size_t)grow0 * H_DIM + col0;
                if (DMODE == 2) *(float2*)(g_h + ofs) = p;
                else            *(float2*)(outp + ofs) = p;
                if (STATS) {
                    csum[nt][0] += v0; csum[nt][1] += v1;
                    if (STATS == 1) { csq[nt][0] += v0 * v0; csq[nt][1] += v1 * v1; }
                }
            }
            if (grow1 < M) {
                float2 p = make_float2(v2, v3);
                size_t ofs = (size_t)grow1 * H_DIM + col0;
                if (DMODE == 2) *(float2*)(g_h + ofs) = p;
                else            *(float2*)(outp + ofs) = p;
                if (STATS) {
                    csum[nt][0] += v2; csum[nt][1] += v3;
                    if (STATS == 1) { csq[nt][0] += v2 * v2; csq[nt][1] += v3 * v3; }
                }
            }
        }
    }

    if (STATS) {
        #pragma unroll
        for (int nt = 0; nt < 6; nt++) {
            #pragma unroll
            for (int j = 0; j < 2; j++) {
                float s = csum[nt][j];
                s += __shfl_xor_sync(0xffffffffu, s, 4);
                s += __shfl_xor_sync(0xffffffffu, s, 8);
                s += __shfl_xor_sync(0xffffffffu, s, 16);
                float qq = 0.f;
                if (STATS == 1) {
                    qq = csq[nt][j];
                    qq += __shfl_xor_sync(0xffffffffu, qq, 4);
                    qq += __shfl_xor_sync(0xffffffffu, qq, 8);
                    qq += __shfl_xor_sync(0xffffffffu, qq, 16);
                }
                if (lane < 4) {
                    int col = warp_n * 48 + nt * 8 + 2 * q + j;
                    sred[warp_m * 96 + col] = s;
                    if (STATS == 1) sred2[warp_m * 96 + col] = qq;
                }
            }
        }
        __syncthreads();
        if (tid < H_DIM) {
            float s = 0.f, qq = 0.f;
            #pragma unroll
            for (int t = 0; t < WARPS_M; t++) {
                s += sred[t * 96 + tid];
                if (STATS == 1) qq += sred2[t * 96 + tid];
            }
            if (STATS == 1) {
                atomicAdd(&g_stats[tid], s);
                atomicAdd(&g_stats[H_DIM + tid], qq);
            } else {
                atomicAdd(&g_stats[2 * H_DIM + tid], s);
            }
        }
    }
}

// ---------------- PairNorm (in place on d_out l1 region) ----------------
__global__ __launch_bounds__(256) void pairnorm_kernel(float* __restrict__ out) {
    int row = blockIdx.x * 8 + (threadIdx.x >> 5);
    if (row >= N_NODES) return;
    int lane = threadIdx.x & 31;
    float* r = out + (size_t)row * H_DIM;
    float v0 = r[lane], v1 = r[lane + 32], v2 = r[lane + 64];
    float ss = v0 * v0 + v1 * v1 + v2 * v2;
    #pragma unroll
    for (int o = 16; o; o >>= 1) ss += __shfl_xor_sync(0xffffffffu, ss, o);
    float sc = PN_SCALE * rsqrtf(1e-6f + ss);
    const float invN = 1.0f / (float)N_NODES;
    r[lane]      = v0 * sc - g_stats[2 * H_DIM + lane]      * invN;
    r[lane + 32] = v1 * sc - g_stats[2 * H_DIM + lane + 32] * invN;
    r[lane + 64] = v2 * sc - g_stats[2 * H_DIM + lane + 64] * invN;
}

// ---------------- launch ----------------
static inline int gemm_smem_bytes(int KD, int BM, int NT) {
    int stride = KD + 4;
    int wm = NT / 64;
    return (BM * stride + 96 * stride + 192 + 2 * wm * 96) * 4;
}

extern "C" void kernel_launch(void* const* d_in, const int* in_sizes, int n_in,
                              void* d_out, int out_size) {
    const float* x     = (const float*)d_in[0];
    const int*   ei    = (const int*)  d_in[1];
    const float* W0    = (const float*)d_in[2];
    const float* b0    = (const float*)d_in[3];
    const float* W1    = (const float*)d_in[4];
    const float* b1    = (const float*)d_in[5];
    const float* gamma = (const float*)d_in[6];
    const float* beta  = (const float*)d_in[7];
    const float* W2    = (const float*)d_in[8];
    const float* b2    = (const float*)d_in[9];

    float* l1 = (float*)d_out;                           // [N, H]
    float* h0 = (float*)d_out + (size_t)N_NODES * H_DIM; // [N, H]

    const int smem0 = gemm_smem_bytes(IN_DIM, 96, 192);  // 104448
    const int smemH = gemm_smem_bytes(H_DIM, 128, 256);  // 93440

    cudaFuncSetAttribute(gemm_kernel<IN_DIM, 96, 192, 2, 0, 0, false, 0>,
                         cudaFuncAttributeMaxDynamicSharedMemorySize, smem0);
    cudaFuncSetAttribute(gemm_kernel<H_DIM, 128, 256, 2, 1, 2, false, 1>,
                         cudaFuncAttributeMaxDynamicSharedMemorySize, smemH);
    cudaFuncSetAttribute(gemm_kernel<H_DIM, 128, 256, 2, 2, 0, true, 2>,
                         cudaFuncAttributeMaxDynamicSharedMemorySize, smemH);

    const int nb_nodes = (N_NODES + 255) / 256;          // 196
    const int nb_quads = (E_EDGES / 4 + 255) / 256;      // 782
    const int nb_edges = (E_EDGES + 255) / 256;          // 3125

    // ---- CSR build (single stream; g_cnt==0 on entry; scan_add re-zeroes it) ----
    hist_kernel<<<nb_quads, 256>>>(ei);
    scan_local_kernel<<<nb_nodes, 256>>>();
    scan_add_kernel<<<nb_nodes, 256>>>(nb_nodes);
    fill_kernel<<<nb_edges, 256>>>(ei);

    // ---- h0 = x @ W0^T + b0 (also zeroes g_stats via block 0); 2 CTAs/SM ----
    gemm_kernel<IN_DIM, 96, 192, 2, 0, 0, false, 0><<<(N_NODES + 95) / 96, 192, smem0>>>(
        x, W0, b0, nullptr, nullptr, h0, N_NODES);

    // ---- g_z = h0 + gather-sum over CSR ----
    aggregate_kernel<<<(N_NODES + 7) / 8, 256>>>(h0);

    // ---- g_h = g_z @ W1^T + b1 ; fused BN stats ----
    gemm_kernel<H_DIM, 128, 256, 2, 1, 2, false, 1><<<(N_NODES + 127) / 128, 256, smemH>>>(
        nullptr, W1, b1, nullptr, nullptr, nullptr, N_NODES);

    // ---- l1 = relu(bn(g_h)) @ W2^T + b2 ; BN finalize in prologue; col-sum fused ----
    gemm_kernel<H_DIM, 128, 256, 2, 2, 0, true, 2><<<(N_NODES + 127) / 128, 256, smemH>>>(
        nullptr, W2, b2, gamma, beta, l1, N_NODES);

    // ---- PairNorm in place ----
    pairnorm_kernel<<<(N_NODES + 7) / 8, 256>>>(l1);
}